// round 12
// baseline (speedup 1.0000x reference)
#include <cuda_runtime.h>
#include <cuda_fp16.h>
#include <math.h>

#define FH 50
#define FW 50
#define FC 1024
#define POOL 7
#define MAXROI 512
#define CELLS (FH * FW)
#define MAPW (CELLS * FC / 8)   // uint4 elements per map

// One contiguous pyramid: [0]=F (rn fp16), [1]=R (vert pair max), [2]=M2 (2x2 max).
// rn is monotone and max returns an input, so max(rn(a),rn(b)) == rn(max(a,b)):
// pooling the fp16 pyramid == rn of the fp32 max (error <= 1 fp16 ulp).
__device__ __half g_pyr[3 * CELLS * FC];
// Per-(roi,bin) geometry: {base_u4_off, ys|ylast<<16, xs|xlast<<16, yn|xn<<8|xstep<<16}
__device__ uint4 g_geom[MAXROI * 49];

// Build F, R, M2 from fp32 (4 source cells per thread; neighbors L2-hot).
// Pure streaming kernel — no geometry work fused (R10's measured-fastest form).
__global__ void __launch_bounds__(256) build_kernel(const float* __restrict__ fm) {
    const int i = blockIdx.x * 256 + threadIdx.x;   // 0 .. 320K-1
    const int cell = i >> 7;
    const int lane = i & 127;
    const int y = cell / FW;
    const int x = cell - y * FW;
    const int xp = min(x + 1, FW - 1);
    const int yp = min(y + 1, FH - 1);

    const int c00 = cell;
    const int c01 = y  * FW + xp;
    const int c10 = yp * FW + x;
    const int c11 = yp * FW + xp;

    const float4* f = reinterpret_cast<const float4*>(fm);
    const int l2 = lane * 2;
    float4 a00 = f[c00 * 256 + l2], b00 = f[c00 * 256 + l2 + 1];
    float4 a01 = f[c01 * 256 + l2], b01 = f[c01 * 256 + l2 + 1];
    float4 a10 = f[c10 * 256 + l2], b10 = f[c10 * 256 + l2 + 1];
    float4 a11 = f[c11 * 256 + l2], b11 = f[c11 * 256 + l2 + 1];

    float4 ra = make_float4(fmaxf(a00.x, a10.x), fmaxf(a00.y, a10.y),
                            fmaxf(a00.z, a10.z), fmaxf(a00.w, a10.w));
    float4 rb = make_float4(fmaxf(b00.x, b10.x), fmaxf(b00.y, b10.y),
                            fmaxf(b00.z, b10.z), fmaxf(b00.w, b10.w));
    float4 qa = make_float4(fmaxf(a01.x, a11.x), fmaxf(a01.y, a11.y),
                            fmaxf(a01.z, a11.z), fmaxf(a01.w, a11.w));
    float4 qb = make_float4(fmaxf(b01.x, b11.x), fmaxf(b01.y, b11.y),
                            fmaxf(b01.z, b11.z), fmaxf(b01.w, b11.w));
    float4 ma = make_float4(fmaxf(ra.x, qa.x), fmaxf(ra.y, qa.y),
                            fmaxf(ra.z, qa.z), fmaxf(ra.w, qa.w));
    float4 mb = make_float4(fmaxf(rb.x, qb.x), fmaxf(rb.y, qb.y),
                            fmaxf(rb.z, qb.z), fmaxf(rb.w, qb.w));

    union { __half2 h[4]; uint4 u; } pf, pr, pm;
    pf.h[0] = __floats2half2_rn(a00.x, a00.y); pf.h[1] = __floats2half2_rn(a00.z, a00.w);
    pf.h[2] = __floats2half2_rn(b00.x, b00.y); pf.h[3] = __floats2half2_rn(b00.z, b00.w);
    pr.h[0] = __floats2half2_rn(ra.x, ra.y);   pr.h[1] = __floats2half2_rn(ra.z, ra.w);
    pr.h[2] = __floats2half2_rn(rb.x, rb.y);   pr.h[3] = __floats2half2_rn(rb.z, rb.w);
    pm.h[0] = __floats2half2_rn(ma.x, ma.y);   pm.h[1] = __floats2half2_rn(ma.z, ma.w);
    pm.h[2] = __floats2half2_rn(mb.x, mb.y);   pm.h[3] = __floats2half2_rn(mb.z, mb.w);

    uint4* pyr = reinterpret_cast<uint4*>(g_pyr);
    pyr[i]            = pf.u;
    pyr[MAPW + i]     = pr.u;
    pyr[2 * MAPW + i] = pm.u;
}

// Tiny standalone geometry kernel: one thread per (roi, bin).
__global__ void __launch_bounds__(256) geom_kernel(const float* __restrict__ rois, int nitems) {
    const int i = blockIdx.x * 256 + threadIdx.x;
    if (i >= nitems) return;
    const int roi = i / 49;
    const int rem = i - roi * 49;
    const int by = rem / POOL;
    const int bx = rem - by * POOL;

    const float4 r = reinterpret_cast<const float4*>(rois)[roi];
    const int h0 = (int)(FH * r.x);
    const int w0 = (int)(FW * r.y);
    const int h1 = (int)(FH * r.z);
    const int w1 = (int)(FW * r.w);
    const int rh = h1 - h0, rw = w1 - w0;
    const int hstep = rh / POOL, wstep = rw / POOL;

    int sh = by * hstep;
    int eh = (by < POOL - 1) ? sh + hstep : rh;
    if (sh == eh) { if (eh < rh) eh += 1; else sh -= 1; }
    int sw = bx * wstep;
    int ew = (bx < POOL - 1) ? sw + wstep : rw;
    if (sw == ew) { if (ew < rw) ew += 1; else sw -= 1; }

    const int ys = max(h0 + sh, 0);
    const int ye = h0 + eh;
    const int xs = max(w0 + sw, 0);
    const int xe = w0 + ew;
    const int h = ye - ys;
    const int w = xe - xs;

    unsigned base_off;  // uint4 offset of the selected map
    int yn, xn, xstep, ylast, xlast;
    if (h >= 2) {
        yn = (h + 1) >> 1; ylast = ye - 2;
        if (w >= 2) { base_off = 2u * MAPW; xn = (w + 1) >> 1; xstep = 2; xlast = xe - 2; }
        else        { base_off = 1u * MAPW; xn = 1; xstep = 2; xlast = xs; }
    } else {
        base_off = 0u; yn = 1; ylast = ys; xn = w; xstep = 1; xlast = xe - 1;
    }

    uint4 g;
    g.x = base_off;
    g.y = (unsigned)ys | ((unsigned)ylast << 16);
    g.z = (unsigned)xs | ((unsigned)xlast << 16);
    g.w = (unsigned)yn | ((unsigned)xn << 8) | ((unsigned)xstep << 16);
    g_geom[i] = g;
}

// One block per (roi, bin). 128 threads = one uint4 lane (8 halves) each.
// Prologue is a single LDG.128 of precomputed geometry + bit extracts.
// (Identical to the R11 pool kernel — best measured: 20.5 us.)
__global__ void __launch_bounds__(128) roipool_kernel(float* __restrict__ out) {
    const int bin = blockIdx.x;      // 0..48
    const int roi = blockIdx.y;

    const uint4 g = g_geom[roi * 49 + bin];
    const uint4* base = reinterpret_cast<const uint4*>(g_pyr) + g.x;
    const int ys    = g.y & 0xFFFF, ylast = (int)(g.y >> 16);
    const int xs    = g.z & 0xFFFF, xlast = (int)(g.z >> 16);
    const int yn    = g.w & 0xFF;
    const int xn    = (g.w >> 8) & 0xFF;
    const int xstep = (int)(g.w >> 16);

    const int t = threadIdx.x;       // uint4 lane (8 halves)
    const __half2 ninf = __float2half2_rn(-INFINITY);
    __half2 a0 = ninf, a1 = ninf, a2 = ninf, a3 = ninf;

    for (int iy = 0; iy < yn; ++iy) {
        const int y = min(ys + 2 * iy, ylast);
        const uint4* row = base + (size_t)(y * FW) * (FC / 8) + t;
        #pragma unroll 2
        for (int ix = 0; ix < xn; ++ix) {
            const int x = min(xs + xstep * ix, xlast);
            union { uint4 u; __half2 h[4]; } v;
            v.u = row[(size_t)x * (FC / 8)];
            a0 = __hmax2(a0, v.h[0]);
            a1 = __hmax2(a1, v.h[1]);
            a2 = __hmax2(a2, v.h[2]);
            a3 = __hmax2(a3, v.h[3]);
        }
    }

    const size_t o = ((size_t)roi * (POOL * POOL) + bin) * FC + (size_t)t * 8;
    float2 f0 = __half22float2(a0), f1 = __half22float2(a1);
    float2 f2 = __half22float2(a2), f3 = __half22float2(a3);
    float4* op = reinterpret_cast<float4*>(out + o);
    op[0] = make_float4(f0.x, f0.y, f1.x, f1.y);
    op[1] = make_float4(f2.x, f2.y, f3.x, f3.y);
}

extern "C" void kernel_launch(void* const* d_in, const int* in_sizes, int n_in,
                              void* d_out, int out_size) {
    const float* features = (const float*)d_in[0];  // [1,50,50,1024] fp32
    const float* rois     = (const float*)d_in[1];  // [N,4] fp32
    const int nrois = in_sizes[1] / 4;
    const int nitems = nrois * 49;

    geom_kernel<<<(nitems + 255) / 256, 256>>>(rois, nitems);
    build_kernel<<<CELLS * FC / 8 / 256, 256>>>(features);

    dim3 grid(POOL * POOL, nrois);
    roipool_kernel<<<grid, 128>>>((float*)d_out);
}

// round 13
// speedup vs baseline: 1.0501x; 1.0501x over previous
#include <cuda_runtime.h>
#include <cuda_fp16.h>
#include <math.h>

#define FH 50
#define FW 50
#define FC 1024
#define POOL 7
#define MAXROI 512
#define CELLS (FH * FW)
#define MAPW (CELLS * FC / 8)     // uint4 elements per map
#define STREAM_BLOCKS (CELLS * FC / 8 / 256)   // 1250

// One contiguous pyramid: [0]=F (rn fp16), [1]=R (vert pair max), [2]=M2 (2x2 max).
// rn is monotone and max returns an input, so max(rn(a),rn(b)) == rn(max(a,b)):
// pooling the fp16 pyramid == rn of the fp32 max (error <= 1 fp16 ulp).
__device__ __half g_pyr[3 * CELLS * FC];
// Per-(roi,bin) geometry: {base_u4_off, ys|ylast<<16, xs|xlast<<16, yn|xn<<8|xstep<<16}
__device__ uint4 g_geom[MAXROI * 49];

// Block-specialized build: blocks [0,1250) stream the pyramid (R10's fastest
// form); blocks >= 1250 compute per-(roi,bin) geometry. One launch total.
__global__ void __launch_bounds__(256) build_kernel(
    const float* __restrict__ fm, const float* __restrict__ rois, int nitems)
{
    if (blockIdx.x >= STREAM_BLOCKS) {
        // ---- geometry blocks: one thread per (roi, bin) ----
        const int i = (blockIdx.x - STREAM_BLOCKS) * 256 + threadIdx.x;
        if (i >= nitems) return;
        const int roi = i / 49;
        const int rem = i - roi * 49;
        const int by = rem / POOL;
        const int bx = rem - by * POOL;

        const float4 r = reinterpret_cast<const float4*>(rois)[roi];
        const int h0 = (int)(FH * r.x);
        const int w0 = (int)(FW * r.y);
        const int h1 = (int)(FH * r.z);
        const int w1 = (int)(FW * r.w);
        const int rh = h1 - h0, rw = w1 - w0;
        const int hstep = rh / POOL, wstep = rw / POOL;

        int sh = by * hstep;
        int eh = (by < POOL - 1) ? sh + hstep : rh;
        if (sh == eh) { if (eh < rh) eh += 1; else sh -= 1; }
        int sw = bx * wstep;
        int ew = (bx < POOL - 1) ? sw + wstep : rw;
        if (sw == ew) { if (ew < rw) ew += 1; else sw -= 1; }

        const int ys = max(h0 + sh, 0);
        const int ye = h0 + eh;
        const int xs = max(w0 + sw, 0);
        const int xe = w0 + ew;
        const int h = ye - ys;
        const int w = xe - xs;

        unsigned base_off;  // uint4 offset of the selected map
        int yn, xn, xstep, ylast, xlast;
        if (h >= 2) {
            yn = (h + 1) >> 1; ylast = ye - 2;
            if (w >= 2) { base_off = 2u * MAPW; xn = (w + 1) >> 1; xstep = 2; xlast = xe - 2; }
            else        { base_off = 1u * MAPW; xn = 1; xstep = 2; xlast = xs; }
        } else {
            base_off = 0u; yn = 1; ylast = ys; xn = w; xstep = 1; xlast = xe - 1;
        }

        uint4 g;
        g.x = base_off;
        g.y = (unsigned)ys | ((unsigned)ylast << 16);
        g.z = (unsigned)xs | ((unsigned)xlast << 16);
        g.w = (unsigned)yn | ((unsigned)xn << 8) | ((unsigned)xstep << 16);
        g_geom[i] = g;
        return;
    }

    // ---- streaming blocks: build F, R, M2 (4 source cells per thread) ----
    const int i = blockIdx.x * 256 + threadIdx.x;   // 0 .. 320K-1
    const int cell = i >> 7;
    const int lane = i & 127;
    const int y = cell / FW;
    const int x = cell - y * FW;
    const int xp = min(x + 1, FW - 1);
    const int yp = min(y + 1, FH - 1);

    const int c00 = cell;
    const int c01 = y  * FW + xp;
    const int c10 = yp * FW + x;
    const int c11 = yp * FW + xp;

    const float4* f = reinterpret_cast<const float4*>(fm);
    const int l2 = lane * 2;
    float4 a00 = f[c00 * 256 + l2], b00 = f[c00 * 256 + l2 + 1];
    float4 a01 = f[c01 * 256 + l2], b01 = f[c01 * 256 + l2 + 1];
    float4 a10 = f[c10 * 256 + l2], b10 = f[c10 * 256 + l2 + 1];
    float4 a11 = f[c11 * 256 + l2], b11 = f[c11 * 256 + l2 + 1];

    float4 ra = make_float4(fmaxf(a00.x, a10.x), fmaxf(a00.y, a10.y),
                            fmaxf(a00.z, a10.z), fmaxf(a00.w, a10.w));
    float4 rb = make_float4(fmaxf(b00.x, b10.x), fmaxf(b00.y, b10.y),
                            fmaxf(b00.z, b10.z), fmaxf(b00.w, b10.w));
    float4 qa = make_float4(fmaxf(a01.x, a11.x), fmaxf(a01.y, a11.y),
                            fmaxf(a01.z, a11.z), fmaxf(a01.w, a11.w));
    float4 qb = make_float4(fmaxf(b01.x, b11.x), fmaxf(b01.y, b11.y),
                            fmaxf(b01.z, b11.z), fmaxf(b01.w, b11.w));
    float4 ma = make_float4(fmaxf(ra.x, qa.x), fmaxf(ra.y, qa.y),
                            fmaxf(ra.z, qa.z), fmaxf(ra.w, qa.w));
    float4 mb = make_float4(fmaxf(rb.x, qb.x), fmaxf(rb.y, qb.y),
                            fmaxf(rb.z, qb.z), fmaxf(rb.w, qb.w));

    union { __half2 h[4]; uint4 u; } pf, pr, pm;
    pf.h[0] = __floats2half2_rn(a00.x, a00.y); pf.h[1] = __floats2half2_rn(a00.z, a00.w);
    pf.h[2] = __floats2half2_rn(b00.x, b00.y); pf.h[3] = __floats2half2_rn(b00.z, b00.w);
    pr.h[0] = __floats2half2_rn(ra.x, ra.y);   pr.h[1] = __floats2half2_rn(ra.z, ra.w);
    pr.h[2] = __floats2half2_rn(rb.x, rb.y);   pr.h[3] = __floats2half2_rn(rb.z, rb.w);
    pm.h[0] = __floats2half2_rn(ma.x, ma.y);   pm.h[1] = __floats2half2_rn(ma.z, ma.w);
    pm.h[2] = __floats2half2_rn(mb.x, mb.y);   pm.h[3] = __floats2half2_rn(mb.z, mb.w);

    uint4* pyr = reinterpret_cast<uint4*>(g_pyr);
    pyr[i]            = pf.u;
    pyr[MAPW + i]     = pr.u;
    pyr[2 * MAPW + i] = pm.u;
}

// One block per (roi, bin). 128 threads = one uint4 lane (8 halves) each.
// Prologue is a single LDG.128 of precomputed geometry + bit extracts.
// (Identical to the R11 pool kernel — best measured: 20.5 us.)
__global__ void __launch_bounds__(128) roipool_kernel(float* __restrict__ out) {
    const int bin = blockIdx.x;      // 0..48
    const int roi = blockIdx.y;

    const uint4 g = g_geom[roi * 49 + bin];
    const uint4* base = reinterpret_cast<const uint4*>(g_pyr) + g.x;
    const int ys    = g.y & 0xFFFF, ylast = (int)(g.y >> 16);
    const int xs    = g.z & 0xFFFF, xlast = (int)(g.z >> 16);
    const int yn    = g.w & 0xFF;
    const int xn    = (g.w >> 8) & 0xFF;
    const int xstep = (int)(g.w >> 16);

    const int t = threadIdx.x;       // uint4 lane (8 halves)
    const __half2 ninf = __float2half2_rn(-INFINITY);
    __half2 a0 = ninf, a1 = ninf, a2 = ninf, a3 = ninf;

    for (int iy = 0; iy < yn; ++iy) {
        const int y = min(ys + 2 * iy, ylast);
        const uint4* row = base + (size_t)(y * FW) * (FC / 8) + t;
        #pragma unroll 2
        for (int ix = 0; ix < xn; ++ix) {
            const int x = min(xs + xstep * ix, xlast);
            union { uint4 u; __half2 h[4]; } v;
            v.u = row[(size_t)x * (FC / 8)];
            a0 = __hmax2(a0, v.h[0]);
            a1 = __hmax2(a1, v.h[1]);
            a2 = __hmax2(a2, v.h[2]);
            a3 = __hmax2(a3, v.h[3]);
        }
    }

    const size_t o = ((size_t)roi * (POOL * POOL) + bin) * FC + (size_t)t * 8;
    float2 f0 = __half22float2(a0), f1 = __half22float2(a1);
    float2 f2 = __half22float2(a2), f3 = __half22float2(a3);
    float4* op = reinterpret_cast<float4*>(out + o);
    op[0] = make_float4(f0.x, f0.y, f1.x, f1.y);
    op[1] = make_float4(f2.x, f2.y, f3.x, f3.y);
}

extern "C" void kernel_launch(void* const* d_in, const int* in_sizes, int n_in,
                              void* d_out, int out_size) {
    const float* features = (const float*)d_in[0];  // [1,50,50,1024] fp32
    const float* rois     = (const float*)d_in[1];  // [N,4] fp32
    const int nrois = in_sizes[1] / 4;
    const int nitems = nrois * 49;
    const int geom_blocks = (nitems + 255) / 256;

    build_kernel<<<STREAM_BLOCKS + geom_blocks, 256>>>(features, rois, nitems);

    dim3 grid(POOL * POOL, nrois);
    roipool_kernel<<<grid, 128>>>((float*)d_out);
}

// round 14
// speedup vs baseline: 1.1239x; 1.0702x over previous
#include <cuda_runtime.h>
#include <cuda_fp16.h>
#include <math.h>

#define FH 50
#define FW 50
#define FC 1024
#define POOL 7
#define CELLS (FH * FW)
#define MAPW (CELLS * FC / 8)   // uint4 elements per map

// One contiguous pyramid: [0]=F (rn fp16), [1]=R (vert pair max), [2]=M2 (2x2 max).
// rn is monotone and max returns an input, so max(rn(a),rn(b)) == rn(max(a,b)):
// pooling the fp16 pyramid == rn of the fp32 max (error <= 1 fp16 ulp).
__device__ __half g_pyr[3 * CELLS * FC];

// Build F, R, M2 from fp32 (4 source cells per thread; neighbors L2-hot).
// R10's measured-fastest form, unchanged.
__global__ void __launch_bounds__(256) build_kernel(const float* __restrict__ fm) {
    const int i = blockIdx.x * 256 + threadIdx.x;   // 0 .. 320K-1
    const int cell = i >> 7;
    const int lane = i & 127;
    const int y = cell / FW;
    const int x = cell - y * FW;
    const int xp = min(x + 1, FW - 1);
    const int yp = min(y + 1, FH - 1);

    const int c00 = cell;
    const int c01 = y  * FW + xp;
    const int c10 = yp * FW + x;
    const int c11 = yp * FW + xp;

    const float4* f = reinterpret_cast<const float4*>(fm);
    const int l2 = lane * 2;
    float4 a00 = f[c00 * 256 + l2], b00 = f[c00 * 256 + l2 + 1];
    float4 a01 = f[c01 * 256 + l2], b01 = f[c01 * 256 + l2 + 1];
    float4 a10 = f[c10 * 256 + l2], b10 = f[c10 * 256 + l2 + 1];
    float4 a11 = f[c11 * 256 + l2], b11 = f[c11 * 256 + l2 + 1];

    float4 ra = make_float4(fmaxf(a00.x, a10.x), fmaxf(a00.y, a10.y),
                            fmaxf(a00.z, a10.z), fmaxf(a00.w, a10.w));
    float4 rb = make_float4(fmaxf(b00.x, b10.x), fmaxf(b00.y, b10.y),
                            fmaxf(b00.z, b10.z), fmaxf(b00.w, b10.w));
    float4 qa = make_float4(fmaxf(a01.x, a11.x), fmaxf(a01.y, a11.y),
                            fmaxf(a01.z, a11.z), fmaxf(a01.w, a11.w));
    float4 qb = make_float4(fmaxf(b01.x, b11.x), fmaxf(b01.y, b11.y),
                            fmaxf(b01.z, b11.z), fmaxf(b01.w, b11.w));
    float4 ma = make_float4(fmaxf(ra.x, qa.x), fmaxf(ra.y, qa.y),
                            fmaxf(ra.z, qa.z), fmaxf(ra.w, qa.w));
    float4 mb = make_float4(fmaxf(rb.x, qb.x), fmaxf(rb.y, qb.y),
                            fmaxf(rb.z, qb.z), fmaxf(rb.w, qb.w));

    union { __half2 h[4]; uint4 u; } pf, pr, pm;
    pf.h[0] = __floats2half2_rn(a00.x, a00.y); pf.h[1] = __floats2half2_rn(a00.z, a00.w);
    pf.h[2] = __floats2half2_rn(b00.x, b00.y); pf.h[3] = __floats2half2_rn(b00.z, b00.w);
    pr.h[0] = __floats2half2_rn(ra.x, ra.y);   pr.h[1] = __floats2half2_rn(ra.z, ra.w);
    pr.h[2] = __floats2half2_rn(rb.x, rb.y);   pr.h[3] = __floats2half2_rn(rb.z, rb.w);
    pm.h[0] = __floats2half2_rn(ma.x, ma.y);   pm.h[1] = __floats2half2_rn(ma.z, ma.w);
    pm.h[2] = __floats2half2_rn(mb.x, mb.y);   pm.h[3] = __floats2half2_rn(mb.z, mb.w);

    uint4* pyr = reinterpret_cast<uint4*>(g_pyr);
    pyr[i]            = pf.u;
    pyr[MAPW + i]     = pr.u;
    pyr[2 * MAPW + i] = pm.u;
}

// 256-thread blocks, TWO bins per block: thread group (tid>>7) owns one bin,
// each of its 128 threads owns one uint4 lane (8 halves). Per-thread logic is
// byte-for-byte R10's pool (inline geometry, same loop); only the packaging
// changes — halves the CTA count while keeping full parallelism.
__global__ void __launch_bounds__(256) roipool_kernel(
    const float* __restrict__ rois,  // [N,4] (y1,x1,y2,x2) normalized
    float* __restrict__ out)         // [N,7,7,1024] fp32
{
    const int bin = blockIdx.x * 2 + (threadIdx.x >> 7);   // 0..49
    if (bin >= 49) return;           // last block's second group idles
    const int roi = blockIdx.y;
    const int by = bin / POOL;
    const int bx = bin - by * POOL;

    const float4 r = reinterpret_cast<const float4*>(rois)[roi];
    const int h0 = (int)(FH * r.x);
    const int w0 = (int)(FW * r.y);
    const int h1 = (int)(FH * r.z);
    const int w1 = (int)(FW * r.w);
    const int rh = h1 - h0;
    const int rw = w1 - w0;
    const int hstep = rh / POOL;
    const int wstep = rw / POOL;

    int sh = by * hstep;
    int eh = (by < POOL - 1) ? sh + hstep : rh;
    if (sh == eh) { if (eh < rh) eh += 1; else sh -= 1; }
    int sw = bx * wstep;
    int ew = (bx < POOL - 1) ? sw + wstep : rw;
    if (sw == ew) { if (ew < rw) ew += 1; else sw -= 1; }

    const int ys = max(h0 + sh, 0);
    const int ye = h0 + eh;          // <= FH
    const int xs = max(w0 + sw, 0);
    const int xe = w0 + ew;          // <= FW
    const int h = ye - ys;
    const int w = xe - xs;

    // Select map + sampling grid (overlapping clamped samples; max idempotent).
    const uint4* base;
    int yn, xn, xstep, ylast, xlast;
    if (h >= 2) {
        yn = (h + 1) >> 1; ylast = ye - 2;
        if (w >= 2) { base = reinterpret_cast<const uint4*>(g_pyr) + 2 * MAPW;
                      xn = (w + 1) >> 1; xstep = 2; xlast = xe - 2; }
        else        { base = reinterpret_cast<const uint4*>(g_pyr) + MAPW;
                      xn = 1; xstep = 2; xlast = xs; }
    } else {        // h == 1: single row from F
        base = reinterpret_cast<const uint4*>(g_pyr);
        yn = 1; ylast = ys; xn = w; xstep = 1; xlast = xe - 1;
    }

    const int t = threadIdx.x & 127; // uint4 lane (8 halves)
    const __half2 ninf = __float2half2_rn(-INFINITY);
    __half2 a0 = ninf, a1 = ninf, a2 = ninf, a3 = ninf;

    for (int iy = 0; iy < yn; ++iy) {
        const int y = min(ys + 2 * iy, ylast);
        const uint4* row = base + (size_t)(y * FW) * (FC / 8) + t;
        #pragma unroll 2
        for (int ix = 0; ix < xn; ++ix) {
            const int x = min(xs + xstep * ix, xlast);
            union { uint4 u; __half2 h[4]; } v;
            v.u = row[(size_t)x * (FC / 8)];
            a0 = __hmax2(a0, v.h[0]);
            a1 = __hmax2(a1, v.h[1]);
            a2 = __hmax2(a2, v.h[2]);
            a3 = __hmax2(a3, v.h[3]);
        }
    }

    const size_t o = ((size_t)roi * (POOL * POOL) + bin) * FC + (size_t)t * 8;
    float2 f0 = __half22float2(a0), f1 = __half22float2(a1);
    float2 f2 = __half22float2(a2), f3 = __half22float2(a3);
    float4* op = reinterpret_cast<float4*>(out + o);
    op[0] = make_float4(f0.x, f0.y, f1.x, f1.y);
    op[1] = make_float4(f2.x, f2.y, f3.x, f3.y);
}

extern "C" void kernel_launch(void* const* d_in, const int* in_sizes, int n_in,
                              void* d_out, int out_size) {
    const float* features = (const float*)d_in[0];  // [1,50,50,1024] fp32
    const float* rois     = (const float*)d_in[1];  // [N,4] fp32
    const int nrois = in_sizes[1] / 4;

    build_kernel<<<CELLS * FC / 8 / 256, 256>>>(features);

    dim3 grid(25, nrois);   // 25 bin-pairs x N rois
    roipool_kernel<<<grid, 256>>>(rois, (float*)d_out);
}